// round 2
// baseline (speedup 1.0000x reference)
#include <cuda_runtime.h>

#define VOCAB  50000
#define EMBED  256
#define MAXLEN 512
#define UNITS  32
#define F1     16
#define BATCH  512

// Scratch: projected embedding table P[v][u] = sum_e emb[v][e]*Wx[e][u], prescaled
// by 2*log2(e) so the recurrence can feed ex2 directly.
__device__ float g_P[VOCAB * UNITS];

#define TANH_SCALE 2.8853900817779268f   // 2*log2(e)

// ---------------------------------------------------------------------------
// Kernel A: P = (emb_table @ Wx) * TANH_SCALE
// Block = 128 threads, covers 128 rows. Thread: ug = t&3 (8 u-cols), s = t>>2
// (row-set of 4 rows). Wx staged once in smem (32 KB), A streamed from global.
// Per 4-e chunk/thread: 4 LDG.128 + 8 LDS.128 + 128 FMA  (~91% FMA fraction).
// ---------------------------------------------------------------------------
__global__ void __launch_bounds__(128) proj_kernel(
    const float* __restrict__ emb, const float* __restrict__ Wx)
{
    __shared__ float sW[EMBED * UNITS];
    const int t = threadIdx.x;
    for (int i = t; i < EMBED * UNITS / 4; i += 128)
        ((float4*)sW)[i] = ((const float4*)Wx)[i];
    __syncthreads();

    const int ug    = t & 3;          // u-group: columns ug*8 .. ug*8+7
    const int s     = t >> 2;         // row-set 0..31
    const int rbase = blockIdx.x * 128 + s * 4;

    float acc[4][8];
    #pragma unroll
    for (int rr = 0; rr < 4; rr++)
        #pragma unroll
        for (int j = 0; j < 8; j++) acc[rr][j] = 0.f;

    const float* arow[4];
    #pragma unroll
    for (int rr = 0; rr < 4; rr++) {
        int r = rbase + rr;
        if (r >= VOCAB) r = VOCAB - 1;          // clamp; stores are guarded
        arow[rr] = emb + (size_t)r * EMBED;
    }

    for (int e0 = 0; e0 < EMBED; e0 += 4) {
        float4 av[4];
        #pragma unroll
        for (int rr = 0; rr < 4; rr++)
            av[rr] = *(const float4*)(arow[rr] + e0);

        #pragma unroll
        for (int ee = 0; ee < 4; ee++) {
            const float4 w0 = *(const float4*)&sW[(e0 + ee) * UNITS + ug * 8];
            const float4 w1 = *(const float4*)&sW[(e0 + ee) * UNITS + ug * 8 + 4];
            #pragma unroll
            for (int rr = 0; rr < 4; rr++) {
                const float a = ((const float*)&av[rr])[ee];
                acc[rr][0] = fmaf(a, w0.x, acc[rr][0]);
                acc[rr][1] = fmaf(a, w0.y, acc[rr][1]);
                acc[rr][2] = fmaf(a, w0.z, acc[rr][2]);
                acc[rr][3] = fmaf(a, w0.w, acc[rr][3]);
                acc[rr][4] = fmaf(a, w1.x, acc[rr][4]);
                acc[rr][5] = fmaf(a, w1.y, acc[rr][5]);
                acc[rr][6] = fmaf(a, w1.z, acc[rr][6]);
                acc[rr][7] = fmaf(a, w1.w, acc[rr][7]);
            }
        }
    }

    #pragma unroll
    for (int rr = 0; rr < 4; rr++) {
        const int r = rbase + rr;
        if (r < VOCAB) {
            float4 o0, o1;
            o0.x = acc[rr][0] * TANH_SCALE; o0.y = acc[rr][1] * TANH_SCALE;
            o0.z = acc[rr][2] * TANH_SCALE; o0.w = acc[rr][3] * TANH_SCALE;
            o1.x = acc[rr][4] * TANH_SCALE; o1.y = acc[rr][5] * TANH_SCALE;
            o1.z = acc[rr][6] * TANH_SCALE; o1.w = acc[rr][7] * TANH_SCALE;
            *(float4*)&g_P[r * UNITS + ug * 8]     = o0;
            *(float4*)&g_P[r * UNITS + ug * 8 + 4] = o1;
        }
    }
}

// ---------------------------------------------------------------------------
// Kernel B: recurrence + head. One warp per batch row, lane u owns h[u].
// Wh column u lives in 32 registers (prescaled by 2*log2(e)).
// tanh(x) = 1 - 2/(1 + e^(2x)) computed as 1 - 2*rcp(1 + ex2(scaled_pre))
// (ex2/rcp approx: ~1e-7 abs error, safe over 512 iterations).
// P-row gather prefetched 4 steps ahead (4*~130 cyc >> L2 latency).
// ---------------------------------------------------------------------------
__global__ void __launch_bounds__(128) rnn_kernel(
    const int*   __restrict__ tokens,
    const float* __restrict__ Wh,
    const float* __restrict__ bvec,
    const float* __restrict__ W1,
    const float* __restrict__ b1,
    const float* __restrict__ W2,
    const float* __restrict__ b2,
    float*       __restrict__ out)
{
    __shared__ int sTok[4 * MAXLEN];
    const int tid  = threadIdx.x;
    const int wid  = tid >> 5;
    const int lane = tid & 31;
    const int b0   = blockIdx.x * 4;

    for (int i = tid; i < 4 * MAXLEN; i += 128)
        sTok[i] = tokens[b0 * MAXLEN + i];
    __syncthreads();

    const int* myTok = sTok + wid * MAXLEN;
    const int  brow  = b0 + wid;

    float wh[32];
    #pragma unroll
    for (int v = 0; v < 32; v++)
        wh[v] = Wh[v * UNITS + lane] * TANH_SCALE;
    const float bu = bvec[lane] * TANH_SCALE;

    float xwv[4];
    #pragma unroll
    for (int j = 0; j < 4; j++)
        xwv[j] = g_P[myTok[j] * UNITS + lane];

    float h = 0.f;
    for (int t0 = 0; t0 < MAXLEN; t0 += 4) {
        #pragma unroll
        for (int j = 0; j < 4; j++) {
            const float xw = xwv[j];
            const int   tn = t0 + j + 4;
            if (tn < MAXLEN)                       // uniform branch, prefetch
                xwv[j] = g_P[myTok[tn] * UNITS + lane];

            float a0 = xw + bu;                    // all terms prescaled
            float a1 = 0.f, a2 = 0.f, a3 = 0.f;
            #pragma unroll
            for (int v = 0; v < 32; v += 4) {
                a0 = fmaf(__shfl_sync(0xffffffffu, h, v + 0), wh[v + 0], a0);
                a1 = fmaf(__shfl_sync(0xffffffffu, h, v + 1), wh[v + 1], a1);
                a2 = fmaf(__shfl_sync(0xffffffffu, h, v + 2), wh[v + 2], a2);
                a3 = fmaf(__shfl_sync(0xffffffffu, h, v + 3), wh[v + 3], a3);
            }
            const float z2 = (a0 + a1) + (a2 + a3);   // = 2*log2(e) * preact
            float e, r;
            asm("ex2.approx.f32 %0, %1;" : "=f"(e) : "f"(z2));
            asm("rcp.approx.f32 %0, %1;" : "=f"(r) : "f"(e + 1.0f));
            h = fmaf(-2.0f, r, 1.0f);
        }
    }

    // Head: f = h@W1 + b1 (16), z = f@W2 + b2, out = sigmoid(z)
    float facc = 0.f;
    #pragma unroll
    for (int v = 0; v < 32; v++) {
        const float hv = __shfl_sync(0xffffffffu, h, v);
        if (lane < F1)
            facc = fmaf(hv, W1[v * F1 + lane], facc);
    }
    float p = 0.f;
    if (lane < F1) p = (facc + b1[lane]) * W2[lane];
    #pragma unroll
    for (int off = 16; off > 0; off >>= 1)
        p += __shfl_xor_sync(0xffffffffu, p, off);

    if (lane == 0) {
        const float z = p + b2[0];
        float e, r;
        asm("ex2.approx.f32 %0, %1;" : "=f"(e) : "f"(-z * 1.4426950408889634f));
        asm("rcp.approx.f32 %0, %1;" : "=f"(r) : "f"(1.0f + e));
        out[brow] = r;
    }
}

// ---------------------------------------------------------------------------
extern "C" void kernel_launch(void* const* d_in, const int* in_sizes, int n_in,
                              void* d_out, int out_size)
{
    const int*   tokens = (const int*)  d_in[0];
    const float* emb    = (const float*)d_in[1];
    const float* Wx     = (const float*)d_in[2];
    const float* Wh     = (const float*)d_in[3];
    const float* b      = (const float*)d_in[4];
    const float* W1     = (const float*)d_in[5];
    const float* b1     = (const float*)d_in[6];
    const float* W2     = (const float*)d_in[7];
    const float* b2     = (const float*)d_in[8];
    float* out = (float*)d_out;

    proj_kernel<<<(VOCAB + 127) / 128, 128>>>(emb, Wx);
    rnn_kernel<<<BATCH / 4, 128>>>(tokens, Wh, b, W1, b1, W2, b2, out);
}